// round 1
// baseline (speedup 1.0000x reference)
#include <cuda_runtime.h>
#include <cstdint>
#include <math.h>

#define B_  2
#define T_  2048
#define C_  1024
#define H_  16
#define HD_ 64
#define NBH_ (B_*H_)     // 32
#define M_   (B_*T_)     // 4096

// Scratch (allocation-free: __device__ globals)
__device__ float g_Q[(size_t)NBH_ * T_ * HD_];
__device__ float g_K[(size_t)NBH_ * T_ * HD_];
__device__ float g_V[(size_t)NBH_ * T_ * HD_];
__device__ float g_Y[(size_t)M_ * C_];

// ---------------------------------------------------------------------------
// Tiled SGEMM: C[M, NCOLS] = A[M,1024] @ W[1024,NCOLS] + bias
// MODE 0: A = x, epilogue scatters into g_Q/g_K/g_V (Q scaled by 0.125)
// MODE 1: A = g_Y, epilogue writes out[m*1024+n]
// 64x64 tile, 256 threads, 4x4 per thread, BK=16.
// ---------------------------------------------------------------------------
template<int NCOLS, int MODE>
__global__ void __launch_bounds__(256) gemm_kernel(const float* __restrict__ A,
                                                   const float* __restrict__ W,
                                                   const float* __restrict__ bias,
                                                   float* __restrict__ out) {
    __shared__ __align__(16) float AsT[16][68];   // [k][m], pad 68 (16B-aligned rows)
    __shared__ float4 Bs[16][16];                 // [k][n/4]
    const int tid = threadIdx.x;
    const int tx = tid & 15, ty = tid >> 4;
    const int m0 = blockIdx.y * 64;
    const int n0 = blockIdx.x * 64;
    const float* Ap = (MODE == 0) ? A : (const float*)g_Y;

    float acc[4][4] = {};
    const int arow = tid >> 2, akq = tid & 3;   // A loader: row 0..63, k-quad 0..3
    const int brow = tid >> 4, bcq = tid & 15;  // B loader: k-row 0..15, n-quad 0..15
    const float* aptr = Ap + (size_t)(m0 + arow) * 1024 + akq * 4;
    const float* wptr = W + (size_t)brow * NCOLS + n0 + bcq * 4;

    for (int k0 = 0; k0 < 1024; k0 += 16) {
        float4 av = *(const float4*)(aptr + k0);
        float4 bv = *(const float4*)(wptr + (size_t)k0 * NCOLS);
        __syncthreads();
        AsT[akq*4+0][arow] = av.x;
        AsT[akq*4+1][arow] = av.y;
        AsT[akq*4+2][arow] = av.z;
        AsT[akq*4+3][arow] = av.w;
        Bs[brow][bcq] = bv;
        __syncthreads();
        #pragma unroll
        for (int kk = 0; kk < 16; kk++) {
            float a_[4], b_[4];
            *(float4*)a_ = *(const float4*)&AsT[kk][4*ty];
            *(float4*)b_ = Bs[kk][tx];
            #pragma unroll
            for (int i = 0; i < 4; i++)
                #pragma unroll
                for (int j = 0; j < 4; j++)
                    acc[i][j] = fmaf(a_[i], b_[j], acc[i][j]);
        }
    }

    #pragma unroll
    for (int j = 0; j < 4; j++) {
        const int n = n0 + 4*tx + j;
        const float bsv = bias[n];
        #pragma unroll
        for (int i = 0; i < 4; i++) {
            const int m = m0 + 4*ty + i;
            const float val = acc[i][j] + bsv;
            if (MODE == 0) {
                const int bb = m >> 11;     // / T_
                const int t  = m & 2047;
                if (n < C_) {
                    const int h = n >> 6, d = n & 63;
                    g_Q[(((size_t)(bb*H_ + h))*T_ + t)*HD_ + d] = val * 0.125f;
                } else if (n < 2*C_) {
                    const int nn = n - C_;
                    const int h = nn >> 6, d = nn & 63;
                    g_K[(((size_t)(bb*H_ + h))*T_ + t)*HD_ + d] = val;
                } else {
                    const int nn = n - 2*C_;
                    const int h = nn >> 6, d = nn & 63;
                    g_V[(((size_t)(bb*H_ + h))*T_ + t)*HD_ + d] = val;
                }
            } else {
                out[(size_t)m * C_ + n] = val;
            }
        }
    }
}

// ---------------------------------------------------------------------------
// Flash attention (fp32): grid (T/64, B*H), 256 threads.
// Q tile 64x64 persistent in smem; per kv-tile: S=QK^T (regs, 4x4/thread),
// causal mask on diagonal tile, online softmax via 16-lane shfl reductions,
// P staged through smem (reusing K buffer), O += P@V. Only qi+1 kv tiles.
// ---------------------------------------------------------------------------
__global__ void __launch_bounds__(256) attn_kernel() {
    extern __shared__ __align__(16) float sm[];
    float* Qs = sm;                 // [64][64]
    float* Ks = sm + 64*64;         // [64][65] K rows; reused as Ps [64][64]
    float* Vt = Ks + 64*65;         // [64][65] transposed: Vt[d][k]
    const int tid = threadIdx.x;
    const int tx = tid & 15, ty = tid >> 4;
    const int qi = blockIdx.x;
    const int bh = blockIdx.y;

    const float* Qg = g_Q + ((size_t)bh * T_ + qi * 64) * HD_;
    const float* Kg = g_K + (size_t)bh * T_ * HD_;
    const float* Vg = g_V + (size_t)bh * T_ * HD_;

    #pragma unroll
    for (int it = 0; it < 4; it++) {
        const int i = tid + it * 256;
        ((float4*)Qs)[i] = ((const float4*)Qg)[i];
    }

    float m_i[4], l_i[4], O[4][4];
    #pragma unroll
    for (int i = 0; i < 4; i++) {
        m_i[i] = -1e30f; l_i[i] = 0.0f;
        #pragma unroll
        for (int j = 0; j < 4; j++) O[i][j] = 0.0f;
    }

    for (int kt = 0; kt <= qi; kt++) {
        __syncthreads();   // prior-iteration Ps/Vt reads complete
        const float* K0 = Kg + (size_t)kt * 64 * HD_;
        const float* V0 = Vg + (size_t)kt * 64 * HD_;
        #pragma unroll
        for (int it = 0; it < 4; it++) {
            const int i = tid + it * 256;
            const int r  = i >> 4;          // kv row 0..63
            const int dq = (i & 15) << 2;   // hd 0..60
            const float4 kv = *(const float4*)(K0 + r * HD_ + dq);
            float* kd = Ks + r * 65 + dq;
            kd[0] = kv.x; kd[1] = kv.y; kd[2] = kv.z; kd[3] = kv.w;
            const float4 vv = *(const float4*)(V0 + r * HD_ + dq);
            Vt[(dq+0)*65 + r] = vv.x;
            Vt[(dq+1)*65 + r] = vv.y;
            Vt[(dq+2)*65 + r] = vv.z;
            Vt[(dq+3)*65 + r] = vv.w;
        }
        __syncthreads();

        // S = Q K^T   (Qs broadcast reads, Ks pad-65 -> conflict-free cols)
        float S[4][4] = {};
        #pragma unroll 4
        for (int d4 = 0; d4 < 16; d4++) {
            float a_[4][4];
            #pragma unroll
            for (int i = 0; i < 4; i++)
                *(float4*)a_[i] = *(const float4*)(Qs + (4*ty+i)*64 + d4*4);
            #pragma unroll
            for (int dd = 0; dd < 4; dd++) {
                float b_[4];
                #pragma unroll
                for (int j = 0; j < 4; j++)
                    b_[j] = Ks[(4*tx+j)*65 + d4*4 + dd];
                #pragma unroll
                for (int i = 0; i < 4; i++)
                    #pragma unroll
                    for (int j = 0; j < 4; j++)
                        S[i][j] = fmaf(a_[i][dd], b_[j], S[i][j]);
            }
        }

        if (kt == qi) {   // diagonal tile: causal mask (same tile offset)
            #pragma unroll
            for (int i = 0; i < 4; i++)
                #pragma unroll
                for (int j = 0; j < 4; j++)
                    if (4*tx + j > 4*ty + i) S[i][j] = -1e30f;
        }

        // Online softmax per row (rows replicated across 16 lanes of half-warp)
        float P[4][4];
        #pragma unroll
        for (int i = 0; i < 4; i++) {
            float rm = fmaxf(fmaxf(S[i][0], S[i][1]), fmaxf(S[i][2], S[i][3]));
            #pragma unroll
            for (int s = 8; s >= 1; s >>= 1)
                rm = fmaxf(rm, __shfl_xor_sync(0xffffffffu, rm, s));
            const float mn = fmaxf(m_i[i], rm);
            const float corr = __expf(m_i[i] - mn);
            m_i[i] = mn;
            float rs = 0.0f;
            #pragma unroll
            for (int j = 0; j < 4; j++) { P[i][j] = __expf(S[i][j] - mn); rs += P[i][j]; }
            #pragma unroll
            for (int s = 8; s >= 1; s >>= 1)
                rs += __shfl_xor_sync(0xffffffffu, rs, s);
            l_i[i] = l_i[i] * corr + rs;
            #pragma unroll
            for (int j = 0; j < 4; j++) O[i][j] *= corr;
        }

        __syncthreads();           // all K reads done -> safe to overwrite with P
        float* Ps = Ks;            // reuse buffer, stride 64
        #pragma unroll
        for (int i = 0; i < 4; i++)
            #pragma unroll
            for (int j = 0; j < 4; j++)
                Ps[(4*ty+i)*64 + 4*tx+j] = P[i][j];
        __syncthreads();

        // O += P @ V   (Ps broadcast, Vt pad-65 conflict-free)
        #pragma unroll 4
        for (int k4 = 0; k4 < 16; k4++) {
            float p_[4][4];
            #pragma unroll
            for (int i = 0; i < 4; i++)
                *(float4*)p_[i] = *(const float4*)(Ps + (4*ty+i)*64 + k4*4);
            #pragma unroll
            for (int kk = 0; kk < 4; kk++) {
                float v_[4];
                #pragma unroll
                for (int j = 0; j < 4; j++)
                    v_[j] = Vt[(4*tx+j)*65 + k4*4 + kk];
                #pragma unroll
                for (int i = 0; i < 4; i++)
                    #pragma unroll
                    for (int j = 0; j < 4; j++)
                        O[i][j] = fmaf(p_[i][kk], v_[j], O[i][j]);
            }
        }
    }

    const int b = bh >> 4, h = bh & 15;
    #pragma unroll
    for (int i = 0; i < 4; i++) {
        const float inv = 1.0f / l_i[i];
        const int t = qi * 64 + 4*ty + i;
        float* yp = g_Y + ((size_t)(b * T_ + t)) * C_ + h * HD_ + 4*tx;
        #pragma unroll
        for (int j = 0; j < 4; j++) yp[j] = O[i][j] * inv;
    }
}

static const int ATTN_SMEM = (64*64 + 64*65 + 64*65) * (int)sizeof(float);  // 49664 B

extern "C" void kernel_launch(void* const* d_in, const int* in_sizes, int n_in,
                              void* d_out, int out_size) {
    const float* x      = (const float*)d_in[0];
    const float* W_attn = (const float*)d_in[1];
    const float* b_attn = (const float*)d_in[2];
    const float* W_proj = (const float*)d_in[3];
    const float* b_proj = (const float*)d_in[4];
    float* out = (float*)d_out;

    cudaFuncSetAttribute(attn_kernel, cudaFuncAttributeMaxDynamicSharedMemorySize, ATTN_SMEM);

    // qkv = x @ W_attn + b_attn, scattered to [B,H,T,HD] Q(.scaled)/K/V
    gemm_kernel<3*C_, 0><<<dim3(3*C_/64, M_/64), 256>>>(x, W_attn, b_attn, nullptr);
    // y = softmax(causal(QK^T)) V  -> g_Y [B,T,C]
    attn_kernel<<<dim3(T_/64, NBH_), 256, ATTN_SMEM>>>();
    // out = y @ W_proj + b_proj
    gemm_kernel<C_, 1><<<dim3(C_/64, M_/64), 256>>>(nullptr, W_proj, b_proj, out);
}

// round 2
// speedup vs baseline: 1.0595x; 1.0595x over previous
#include <cuda_runtime.h>
#include <cstdint>
#include <math.h>

#define B_  2
#define T_  2048
#define C_  1024
#define H_  16
#define HD_ 64
#define NBH_ (B_*H_)     // 32
#define M_   (B_*T_)     // 4096

// Scratch (allocation-free: __device__ globals)
__device__ float g_Q[(size_t)NBH_ * T_ * HD_];
__device__ float g_K[(size_t)NBH_ * T_ * HD_];
__device__ float g_V[(size_t)NBH_ * T_ * HD_];
__device__ float g_Y[(size_t)M_ * C_];

// ---------------------------------------------------------------------------
// Tiled SGEMM: C[M, NCOLS] = A[M,1024] @ W[1024,NCOLS] + bias
// 128x128 tile, 256 threads, 8x8 microtile (split 4+4 rows/cols 64 apart), BK=8.
// MODE 0: A = x, epilogue scatters into g_Q/g_K/g_V (Q scaled by 0.125)
// MODE 1: A = g_Y, epilogue writes out.
// ---------------------------------------------------------------------------
template<int NCOLS, int MODE>
__global__ void __launch_bounds__(256) gemm_kernel(const float* __restrict__ A,
                                                   const float* __restrict__ W,
                                                   const float* __restrict__ bias,
                                                   float* __restrict__ out) {
    __shared__ __align__(16) float AsT[8][132];   // [k][m], pad 132 (rows 16B-aligned)
    __shared__ __align__(16) float Bs[8][128];    // [k][n]
    const int tid = threadIdx.x;
    const int tx = tid & 15, ty = tid >> 4;
    const int m0 = blockIdx.y * 128;
    const int n0 = blockIdx.x * 128;
    const float* Ap = (MODE == 0) ? A : (const float*)g_Y;

    float acc[8][8] = {};
    const int arow = tid >> 1, akq = tid & 1;       // A loader: row 0..127, k-quad 0..1
    const int brow = tid >> 5, bcol = (tid & 31)*4; // B loader: k 0..7, n 0..124
    const float* aptr = Ap + (size_t)(m0 + arow) * 1024 + akq * 4;
    const float* wptr = W + (size_t)brow * NCOLS + n0 + bcol;

    for (int k0 = 0; k0 < 1024; k0 += 8) {
        const float4 av = *(const float4*)(aptr + k0);
        const float4 bv = *(const float4*)(wptr + (size_t)k0 * NCOLS);
        __syncthreads();
        AsT[akq*4+0][arow] = av.x;
        AsT[akq*4+1][arow] = av.y;
        AsT[akq*4+2][arow] = av.z;
        AsT[akq*4+3][arow] = av.w;
        *(float4*)&Bs[brow][bcol] = bv;
        __syncthreads();
        #pragma unroll
        for (int kk = 0; kk < 8; kk++) {
            float a_[8], b_[8];
            *(float4*)&a_[0] = *(const float4*)&AsT[kk][4*ty];
            *(float4*)&a_[4] = *(const float4*)&AsT[kk][64 + 4*ty];
            *(float4*)&b_[0] = *(const float4*)&Bs[kk][4*tx];
            *(float4*)&b_[4] = *(const float4*)&Bs[kk][64 + 4*tx];
            #pragma unroll
            for (int i = 0; i < 8; i++)
                #pragma unroll
                for (int j = 0; j < 8; j++)
                    acc[i][j] = fmaf(a_[i], b_[j], acc[i][j]);
        }
    }

    #pragma unroll
    for (int j = 0; j < 8; j++) {
        const int n = n0 + ((j < 4) ? (4*tx + j) : (64 + 4*tx + j - 4));
        const float bsv = bias[n];
        #pragma unroll
        for (int i = 0; i < 8; i++) {
            const int m = m0 + ((i < 4) ? (4*ty + i) : (64 + 4*ty + i - 4));
            const float val = acc[i][j] + bsv;
            if (MODE == 0) {
                const int bb = m >> 11;     // / T_
                const int t  = m & 2047;
                if (n < C_) {
                    const int h = n >> 6, d = n & 63;
                    g_Q[(((size_t)(bb*H_ + h))*T_ + t)*HD_ + d] = val * 0.125f;
                } else if (n < 2*C_) {
                    const int nn = n - C_;
                    const int h = nn >> 6, d = nn & 63;
                    g_K[(((size_t)(bb*H_ + h))*T_ + t)*HD_ + d] = val;
                } else {
                    const int nn = n - 2*C_;
                    const int h = nn >> 6, d = nn & 63;
                    g_V[(((size_t)(bb*H_ + h))*T_ + t)*HD_ + d] = val;
                }
            } else {
                out[(size_t)m * C_ + n] = val;
            }
        }
    }
}

// ---------------------------------------------------------------------------
// Flash attention (fp32): grid (T/128, B*H), 256 threads.
// Q tile 128x64 in smem; KV tile 64. Each thread owns 8 rows (4ty+i, 64+4ty+i)
// x 4 cols (4tx+j). Online softmax via 16-lane shuffles. P staged via smem.
// Only 2*qi+2 kv-tiles per q-tile; heavy q-tiles scheduled first.
// ---------------------------------------------------------------------------
__global__ void __launch_bounds__(256) attn_kernel() {
    extern __shared__ __align__(16) float sm[];
    float* Qs = sm;                 // [128][64]
    float* Ks = Qs + 128*64;        // [64][65]   K rows
    float* Vt = Ks + 64*65;         // [64][65]   transposed: Vt[d][k]
    float* Ps = Vt + 64*65;         // [128][64]
    const int tid = threadIdx.x;
    const int tx = tid & 15, ty = tid >> 4;
    const int qi = gridDim.x - 1 - blockIdx.x;   // heavy tiles first
    const int bh = blockIdx.y;

    const float* Qg = g_Q + ((size_t)bh * T_ + qi * 128) * HD_;
    const float* Kg = g_K + (size_t)bh * T_ * HD_;
    const float* Vg = g_V + (size_t)bh * T_ * HD_;

    #pragma unroll
    for (int it = 0; it < 8; it++) {
        const int i = tid + it * 256;
        ((float4*)Qs)[i] = ((const float4*)Qg)[i];
    }

    float m_i[8], l_i[8], O[8][4];
    #pragma unroll
    for (int i = 0; i < 8; i++) {
        m_i[i] = -1e30f; l_i[i] = 0.0f;
        #pragma unroll
        for (int j = 0; j < 4; j++) O[i][j] = 0.0f;
    }

    const int ktEnd = 2 * qi + 1;
    for (int kt = 0; kt <= ktEnd; kt++) {
        __syncthreads();   // prior-iteration Ps/Vt reads complete
        const float* K0 = Kg + (size_t)kt * 64 * HD_;
        const float* V0 = Vg + (size_t)kt * 64 * HD_;
        #pragma unroll
        for (int it = 0; it < 4; it++) {
            const int i = tid + it * 256;
            const int r  = i >> 4;          // kv row 0..63
            const int dq = (i & 15) << 2;   // hd 0..60
            const float4 kv = *(const float4*)(K0 + r * HD_ + dq);
            float* kd = Ks + r * 65 + dq;
            kd[0] = kv.x; kd[1] = kv.y; kd[2] = kv.z; kd[3] = kv.w;
            const float4 vv = *(const float4*)(V0 + r * HD_ + dq);
            Vt[(dq+0)*65 + r] = vv.x;
            Vt[(dq+1)*65 + r] = vv.y;
            Vt[(dq+2)*65 + r] = vv.z;
            Vt[(dq+3)*65 + r] = vv.w;
        }
        __syncthreads();

        // S = Q K^T
        float S[8][4] = {};
        #pragma unroll 4
        for (int d4 = 0; d4 < 16; d4++) {
            float b_[4][4];
            #pragma unroll
            for (int dd = 0; dd < 4; dd++)
                #pragma unroll
                for (int j = 0; j < 4; j++)
                    b_[dd][j] = Ks[(4*tx+j)*65 + d4*4 + dd];
            #pragma unroll
            for (int g = 0; g < 2; g++) {
                #pragma unroll
                for (int i = 0; i < 4; i++) {
                    float a_[4];
                    *(float4*)a_ = *(const float4*)(Qs + (g*64 + 4*ty + i)*64 + d4*4);
                    #pragma unroll
                    for (int dd = 0; dd < 4; dd++)
                        #pragma unroll
                        for (int j = 0; j < 4; j++)
                            S[g*4+i][j] = fmaf(a_[dd], b_[dd][j], S[g*4+i][j]);
                }
            }
        }

        if (kt >= 2*qi) {   // diagonal tiles: causal mask
            #pragma unroll
            for (int g = 0; g < 2; g++)
                #pragma unroll
                for (int i = 0; i < 4; i++)
                    #pragma unroll
                    for (int j = 0; j < 4; j++) {
                        const int r = qi*128 + g*64 + 4*ty + i;
                        const int c = kt*64 + 4*tx + j;
                        if (c > r) S[g*4+i][j] = -1e30f;
                    }
        }

        // Online softmax per row (rows replicated across 16 lanes)
        #pragma unroll
        for (int ii = 0; ii < 8; ii++) {
            float rm = fmaxf(fmaxf(S[ii][0], S[ii][1]), fmaxf(S[ii][2], S[ii][3]));
            #pragma unroll
            for (int s = 8; s >= 1; s >>= 1)
                rm = fmaxf(rm, __shfl_xor_sync(0xffffffffu, rm, s));
            const float mn = fmaxf(m_i[ii], rm);
            const float corr = __expf(m_i[ii] - mn);
            m_i[ii] = mn;
            float rs = 0.0f;
            #pragma unroll
            for (int j = 0; j < 4; j++) { S[ii][j] = __expf(S[ii][j] - mn); rs += S[ii][j]; }
            #pragma unroll
            for (int s = 8; s >= 1; s >>= 1)
                rs += __shfl_xor_sync(0xffffffffu, rs, s);
            l_i[ii] = l_i[ii] * corr + rs;
            #pragma unroll
            for (int j = 0; j < 4; j++) O[ii][j] *= corr;
        }

        // stage P (float4 rows, conflict-free)
        #pragma unroll
        for (int g = 0; g < 2; g++)
            #pragma unroll
            for (int i = 0; i < 4; i++) {
                float4 pv = make_float4(S[g*4+i][0], S[g*4+i][1], S[g*4+i][2], S[g*4+i][3]);
                *(float4*)(Ps + (g*64 + 4*ty + i)*64 + 4*tx) = pv;
            }
        __syncthreads();

        // O += P @ V
        #pragma unroll 4
        for (int k4 = 0; k4 < 16; k4++) {
            float v_[4][4];
            #pragma unroll
            for (int kk = 0; kk < 4; kk++)
                #pragma unroll
                for (int j = 0; j < 4; j++)
                    v_[kk][j] = Vt[(4*tx+j)*65 + k4*4 + kk];
            #pragma unroll
            for (int g = 0; g < 2; g++) {
                #pragma unroll
                for (int i = 0; i < 4; i++) {
                    float p_[4];
                    *(float4*)p_ = *(const float4*)(Ps + (g*64 + 4*ty + i)*64 + k4*4);
                    #pragma unroll
                    for (int kk = 0; kk < 4; kk++)
                        #pragma unroll
                        for (int j = 0; j < 4; j++)
                            O[g*4+i][j] = fmaf(p_[kk], v_[kk][j], O[g*4+i][j]);
                }
            }
        }
    }

    const int b = bh >> 4, h = bh & 15;
    #pragma unroll
    for (int g = 0; g < 2; g++)
        #pragma unroll
        for (int i = 0; i < 4; i++) {
            const int ii = g*4 + i;
            const float inv = 1.0f / l_i[ii];
            const int t = qi*128 + g*64 + 4*ty + i;
            float* yp = g_Y + ((size_t)(b * T_ + t)) * C_ + h * HD_ + 4*tx;
            #pragma unroll
            for (int j = 0; j < 4; j++) yp[j] = O[ii][j] * inv;
        }
}

static const int ATTN_SMEM = (128*64 + 64*65 + 64*65 + 128*64) * (int)sizeof(float); // 98816 B

extern "C" void kernel_launch(void* const* d_in, const int* in_sizes, int n_in,
                              void* d_out, int out_size) {
    const float* x      = (const float*)d_in[0];
    const float* W_attn = (const float*)d_in[1];
    const float* b_attn = (const float*)d_in[2];
    const float* W_proj = (const float*)d_in[3];
    const float* b_proj = (const float*)d_in[4];
    float* out = (float*)d_out;

    cudaFuncSetAttribute(attn_kernel, cudaFuncAttributeMaxDynamicSharedMemorySize, ATTN_SMEM);

    gemm_kernel<3*C_, 0><<<dim3(3*C_/128, M_/128), 256>>>(x, W_attn, b_attn, nullptr);
    attn_kernel<<<dim3(T_/128, NBH_), 256, ATTN_SMEM>>>();
    gemm_kernel<C_, 1><<<dim3(C_/128, M_/128), 256>>>(nullptr, W_proj, b_proj, out);
}